// round 11
// baseline (speedup 1.0000x reference)
#include <cuda_runtime.h>
#include <cuda_fp16.h>

#define DTC (1.0f/64.0f)
#define VOLR 64.0f
#define NSTEPS 64
#define NK 32
#define NRAYS 16384

// Channel-vector fp16 template: entry (k,z,y,x) = 8 halves (16B):
// {c0,c1,c2,c3}@x , {c0,c1,c2,c3}@x+1  (x+1 clamped at edge, never used there)
__device__ uint4 g_templ[NK * 16 * 16 * 16];

__global__ void repack_kernel(const float* __restrict__ t) {
    int idx = blockIdx.x * blockDim.x + threadIdx.x;  // over NK*4096 voxels
    if (idx >= NK * 4096) return;
    int k = idx >> 12;
    int v = idx & 4095;          // z*256 + y*16 + x
    int x = v & 15;
    int x1 = (x < 15) ? 1 : 0;
    const float* src = t + (size_t)k * 4 * 4096 + v;
    __half h[8];
    #pragma unroll
    for (int c = 0; c < 4; c++) {
        h[c]     = __float2half_rn(src[c * 4096]);
        h[4 + c] = __float2half_rn(src[c * 4096 + x1]);
    }
    g_templ[idx] = *reinterpret_cast<uint4*>(h);
}

__device__ __forceinline__ float warp_sum(float v) {
    #pragma unroll
    for (int off = 16; off; off >>= 1)
        v += __shfl_xor_sync(0xffffffffu, v, off);
    return v;
}

// Trilinear sample of 4 channels at grid coords (gz,gy,gx) in [0,15].
// x,y lerps in packed fp16 (HSUB2/HFMA2), z lerp in fp32.
__device__ __forceinline__ void trilerp(const uint4* __restrict__ tk,
                                        float gz, float gy, float gx,
                                        float& v0, float& v1, float& v2, float& v3)
{
    float izf = fminf(floorf(gz), 14.f);
    float iyf = fminf(floorf(gy), 14.f);
    float ixf = fminf(floorf(gx), 14.f);
    float fz = gz - izf, fy = gy - iyf, fx = gx - ixf;   // in [0,1]
    int iz = (int)izf, iy = (int)iyf, ix = (int)ixf;

    __half2 fx2 = __float2half2_rn(fx);
    __half2 fy2 = __float2half2_rn(fy);

    const uint4* p = tk + (iz << 8) + (iy << 4) + ix;
    uint4 e00 = __ldg(p);            // (z0,y0)
    uint4 e01 = __ldg(p + 16);       // (z0,y1)
    uint4 e10 = __ldg(p + 256);      // (z1,y0)
    uint4 e11 = __ldg(p + 272);      // (z1,y1)

    // x-lerp: channels {c0,c1} in a, {c2,c3} in b
    #define XL(e, a, b)                                                      \
    {                                                                        \
        __half2 lo0 = *(const __half2*)&(e).x, lo1 = *(const __half2*)&(e).y;\
        __half2 hi0 = *(const __half2*)&(e).z, hi1 = *(const __half2*)&(e).w;\
        a = __hfma2(fx2, __hsub2(hi0, lo0), lo0);                            \
        b = __hfma2(fx2, __hsub2(hi1, lo1), lo1);                            \
    }
    __half2 a00, b00, a01, b01, a10, b10, a11, b11;
    XL(e00, a00, b00); XL(e01, a01, b01);
    XL(e10, a10, b10); XL(e11, a11, b11);
    #undef XL

    // y-lerp (fp16 packed)
    __half2 z0a = __hfma2(fy2, __hsub2(a01, a00), a00);
    __half2 z0b = __hfma2(fy2, __hsub2(b01, b00), b00);
    __half2 z1a = __hfma2(fy2, __hsub2(a11, a10), a10);
    __half2 z1b = __hfma2(fy2, __hsub2(b11, b10), b10);

    // convert, z-lerp in fp32
    float2 f0a = __half22float2(z0a), f0b = __half22float2(z0b);
    float2 f1a = __half22float2(z1a), f1b = __half22float2(z1b);
    v0 = fmaf(fz, f1a.x - f0a.x, f0a.x);
    v1 = fmaf(fz, f1a.y - f0a.y, f0a.y);
    v2 = fmaf(fz, f1b.x - f0b.x, f0b.x);
    v3 = fmaf(fz, f1b.y - f0b.y, f0b.y);
}

__global__ void __launch_bounds__(128, 12) raymarch_kernel(
    const float* __restrict__ raypos, const float* __restrict__ raydir,
    const float* __restrict__ tminmax, const float* __restrict__ primpos,
    const float* __restrict__ primrot, const float* __restrict__ primscale,
    float* __restrict__ out)
{
    const int lane = threadIdx.x & 31;
    const int ray  = blockIdx.x * 4 + (threadIdx.x >> 5);
    const unsigned FULL = 0xffffffffu;

    // lane k handles primitive k (K == 32 == warp width)
    const int k = lane;
    const float px = primpos[k*3+0], py = primpos[k*3+1], pz = primpos[k*3+2];
    const float r00 = primrot[k*9+0], r01 = primrot[k*9+1], r02 = primrot[k*9+2];
    const float r10 = primrot[k*9+3], r11 = primrot[k*9+4], r12 = primrot[k*9+5];
    const float r20 = primrot[k*9+6], r21 = primrot[k*9+7], r22 = primrot[k*9+8];
    const float s0 = primscale[k*3+0], s1 = primscale[k*3+1], s2 = primscale[k*3+2];

    const float rpx = raypos[ray*3+0], rpy = raypos[ray*3+1], rpz = raypos[ray*3+2];
    const float rdx = raydir[ray*3+0], rdy = raydir[ray*3+1], rdz = raydir[ray*3+2];
    const float tmin = tminmax[ray*2+0], tmax = tminmax[ray*2+1];

    // Grid-space affine: g(t) = Bg + t*Dg, inside <=> all axes in [0,15]
    const float wx = rpx - px, wy = rpy - py, wz = rpz - pz;
    const float Bz = fmaf(s0 * fmaf(r00, wx, fmaf(r01, wy, r02 * wz)), 7.5f, 7.5f);
    const float By = fmaf(s1 * fmaf(r10, wx, fmaf(r11, wy, r12 * wz)), 7.5f, 7.5f);
    const float Bx = fmaf(s2 * fmaf(r20, wx, fmaf(r21, wy, r22 * wz)), 7.5f, 7.5f);
    const float Dz = 7.5f * (s0 * fmaf(r00, rdx, fmaf(r01, rdy, r02 * rdz)));
    const float Dy = 7.5f * (s1 * fmaf(r10, rdx, fmaf(r11, rdy, r12 * rdz)));
    const float Dx = 7.5f * (s2 * fmaf(r20, rdx, fmaf(r21, rdy, r22 * rdz)));

    // Per-lane slab interval in t for g in [0,15] (conservative, widened 1 step)
    float ta = -1e30f, tb = 1e30f;
    {
        const float BB[3] = {Bz, By, Bx};
        const float DD[3] = {Dz, Dy, Dx};
        #pragma unroll
        for (int a = 0; a < 3; a++) {
            float B = BB[a], D = DD[a];
            if (fabsf(D) < 1e-9f) {
                if (B < 0.f || B > 15.f) { ta = 1e30f; tb = -1e30f; }
            } else {
                float inv = 1.0f / D;
                float t0 = (0.f  - B) * inv;
                float t1 = (15.f - B) * inv;
                float lo = fminf(t0, t1), hi = fmaxf(t0, t1);
                ta = fmaxf(ta, lo); tb = fminf(tb, hi);
            }
        }
    }
    int ia, ib;
    if (ta > tb) { ia = NSTEPS; ib = -1; }
    else {
        float iaf = floorf((ta - tmin) * VOLR) - 1.0f;
        float ibf = ceilf((tb - tmin) * VOLR) + 1.0f;
        ia = (int)fminf(fmaxf(iaf, 0.0f), (float)NSTEPS);
        ib = (int)fminf(fmaxf(ibf, -1.0f), (float)(NSTEPS - 1));
    }
    int i_start = ia, i_end = ib;
    #pragma unroll
    for (int off = 16; off; off >>= 1) {
        i_start = min(i_start, __shfl_xor_sync(FULL, i_start, off));
        i_end   = max(i_end,   __shfl_xor_sync(FULL, i_end,   off));
    }

    // Uniform step limit from tmax: i valid iff fmaf(i,DTC,tmin) < tmax (exact fixup)
    int ilim = (int)ceilf((tmax - tmin) * VOLR);
    ilim = max(0, min(ilim, NSTEPS));
    while (ilim > 0 && fmaf((float)(ilim - 1), DTC, tmin) >= tmax) ilim--;
    while (ilim < NSTEPS && fmaf((float)ilim, DTC, tmin) < tmax) ilim++;
    i_end = min(i_end, ilim - 1);

    const uint4* __restrict__ tk = g_templ + (k << 12);

    float acc0 = 0.f, acc1 = 0.f, acc2 = 0.f;   // per-lane deferred rgb accum
    float alpha = 0.f;                           // identical across lanes

    for (int i = i_start; i <= i_end; i++) {
        float t = fmaf((float)i, DTC, tmin);
        float gz = fmaf(t, Dz, Bz), gy = fmaf(t, Dy, By), gx = fmaf(t, Dx, Bx);
        bool inside = fminf(fminf(gz, gy), gx) >= 0.f &&
                      fmaxf(fmaxf(gz, gy), gx) <= 15.f;

        if (!__ballot_sync(FULL, inside)) continue;  // exact no-op step

        float v0 = 0.f, v1 = 0.f, v2 = 0.f, v3 = 0.f;
        if (inside) trilerp(tk, gz, gy, gx, v0, v1, v2, v3);

        // only alpha needs the per-step cross-lane sum
        float sa = warp_sum(v3);
        // sa >= 0 (softplus alpha), so only clamp the top; alpha monotone
        float na = fminf(fmaf(sa, DTC, alpha), 1.0f);
        float contrib = na - alpha;
        acc0 = fmaf(v0, contrib, acc0);
        acc1 = fmaf(v1, contrib, acc1);
        acc2 = fmaf(v2, contrib, acc2);
        alpha = na;
        if (alpha >= 1.0f) break;        // uniform; further steps are exact no-ops
    }

    // one-time rgb reduction over primitives (lanes)
    float r0 = warp_sum(acc0);
    float r1 = warp_sum(acc1);
    float r2 = warp_sum(acc2);

    // planes: [0..2]=rgb, [3]=alpha, [4..6]=rgb, [7]=alpha
    if (lane == 0) {
        out[0 * NRAYS + ray] = r0;
        out[1 * NRAYS + ray] = r1;
        out[2 * NRAYS + ray] = r2;
        out[3 * NRAYS + ray] = alpha;
        out[4 * NRAYS + ray] = r0;
        out[5 * NRAYS + ray] = r1;
        out[6 * NRAYS + ray] = r2;
        out[7 * NRAYS + ray] = alpha;
    }
}

extern "C" void kernel_launch(void* const* d_in, const int* in_sizes, int n_in,
                              void* d_out, int out_size) {
    const float* raypos    = (const float*)d_in[0];
    const float* raydir    = (const float*)d_in[1];
    const float* tminmax   = (const float*)d_in[2];
    const float* primpos   = (const float*)d_in[3];
    const float* primrot   = (const float*)d_in[4];
    const float* primscale = (const float*)d_in[5];
    const float* templ     = (const float*)d_in[6];
    float* out = (float*)d_out;

    repack_kernel<<<(NK * 4096 + 255) / 256, 256>>>(templ);
    raymarch_kernel<<<NRAYS / 4, 128>>>(raypos, raydir, tminmax,
                                        primpos, primrot, primscale, out);
}